// round 1
// baseline (speedup 1.0000x reference)
#include <cuda_runtime.h>
#include <math.h>

// ---------------------------------------------------------------------------
// Problem constants
// ---------------------------------------------------------------------------
#define BB   16
#define LL1  512
#define LL2  512
#define EMB  300
#define AH   256
#define ATT  250
#define HH   128
#define ATT_IN 812            // EMB + 2*AH
#define RNN_IN 1280           // 2*AH*2 + 2*H
#define GATES  512            // 4*H
#define ROWS1 (BB*LL1)        // 8192
#define ROWS2 (BB*LL2)        // 8192

// ---------------------------------------------------------------------------
// Scratch (static __device__ arrays; no allocations allowed)
// ---------------------------------------------------------------------------
__device__ float g_x1_att[ROWS1 * ATT_IN];   // [8192, 812]
__device__ float g_x2_att[ROWS2 * ATT_IN];   // [8192, 812]
__device__ float g_r1[ROWS1 * ATT];          // [8192, 250]
__device__ float g_r2[ROWS2 * ATT];          // [8192, 250]
__device__ float g_scores[ROWS1 * LL2];      // [8192, 512]
__device__ float g_x1cat[ROWS1 * RNN_IN];    // [8192, 1280]
__device__ float g_gin_f[ROWS1 * GATES];     // [8192, 512]
__device__ float g_gin_b[ROWS1 * GATES];     // [8192, 512]

// ---------------------------------------------------------------------------
// Concat kernels
// ---------------------------------------------------------------------------
__global__ void concat_att_kernel(const float* __restrict__ w,
                                  const float* __restrict__ a0,
                                  const float* __restrict__ a1,
                                  float* __restrict__ out, int rows) {
    int idx = blockIdx.x * blockDim.x + threadIdx.x;
    int total = rows * ATT_IN;
    if (idx >= total) return;
    int r = idx / ATT_IN;
    int d = idx - r * ATT_IN;
    float v;
    if (d < EMB)            v = w[r * EMB + d];
    else if (d < EMB + AH)  v = a0[r * AH + (d - EMB)];
    else                    v = a1[r * AH + (d - EMB - AH)];
    out[idx] = v;
}

__global__ void init_cat_kernel(const float* __restrict__ a0,
                                const float* __restrict__ a1,
                                float* __restrict__ cat, int rows) {
    int idx = blockIdx.x * blockDim.x + threadIdx.x;
    int total = rows * (2 * AH);
    if (idx >= total) return;
    int r = idx / (2 * AH);
    int d = idx - r * (2 * AH);
    float v = (d < AH) ? a0[r * AH + d] : a1[r * AH + (d - AH)];
    cat[(long long)r * RNN_IN + d] = v;
}

// ---------------------------------------------------------------------------
// Generic tiled SGEMM: C = epilogue(A @ op(B))
//   A: [M,K] row-major. BT=true: B is [N,K] row-major (NT). BT=false: B is
//   [K,N] row-major (NN). Batched via blockIdx.z with element strides.
//   epilogue: (+bias[n]) -> relu? -> (*cscale[n])
// Tile: 128x128x8, 256 threads, 8x8 microtile.
// ---------------------------------------------------------------------------
template <bool BT>
__global__ __launch_bounds__(256, 2)
void gemm_kernel(const float* __restrict__ A, const float* __restrict__ Bm,
                 const float* __restrict__ bias, const float* __restrict__ cscale,
                 float* __restrict__ C,
                 int M, int N, int K, int ldc,
                 long long sA, long long sB, long long sC, int doRelu) {
    __shared__ float As[8][132];
    __shared__ float Bs[8][132];

    const float* Ab = A + (long long)blockIdx.z * sA;
    const float* Bb = Bm + (long long)blockIdx.z * sB;
    float* Cb = C + (long long)blockIdx.z * sC;

    int m0 = blockIdx.y * 128;
    int n0 = blockIdx.x * 128;
    int t = threadIdx.x;
    int tx = t & 15;        // 0..15 -> N direction
    int ty = t >> 4;        // 0..15 -> M direction

    float acc[8][8];
#pragma unroll
    for (int i = 0; i < 8; i++)
#pragma unroll
        for (int j = 0; j < 8; j++) acc[i][j] = 0.f;

    int nk = (K + 7) >> 3;
    for (int kt = 0; kt < nk; kt++) {
        int k0 = kt << 3;
        // ---- load A tile: 128 rows x 8 k
#pragma unroll
        for (int i = 0; i < 4; i++) {
            int e = t + i * 256;              // 0..1023
            int r = e >> 3, c = e & 7;
            int gm = m0 + r, gk = k0 + c;
            As[c][r] = (gm < M && gk < K) ? Ab[(long long)gm * K + gk] : 0.f;
        }
        // ---- load B tile
#pragma unroll
        for (int i = 0; i < 4; i++) {
            int e = t + i * 256;
            if (BT) {                         // B [N,K]
                int r = e >> 3, c = e & 7;
                int gn = n0 + r, gk = k0 + c;
                Bs[c][r] = (gn < N && gk < K) ? Bb[(long long)gn * K + gk] : 0.f;
            } else {                          // B [K,N]
                int r = e >> 7, c = e & 127;
                int gk = k0 + r, gn = n0 + c;
                Bs[r][c] = (gk < K && gn < N) ? Bb[(long long)gk * N + gn] : 0.f;
            }
        }
        __syncthreads();
#pragma unroll
        for (int k = 0; k < 8; k++) {
            float a[8], b[8];
#pragma unroll
            for (int i = 0; i < 8; i++) a[i] = As[k][ty * 8 + i];
#pragma unroll
            for (int j = 0; j < 8; j++) b[j] = Bs[k][tx * 8 + j];
#pragma unroll
            for (int i = 0; i < 8; i++)
#pragma unroll
                for (int j = 0; j < 8; j++) acc[i][j] += a[i] * b[j];
        }
        __syncthreads();
    }

    // ---- epilogue + store
#pragma unroll
    for (int i = 0; i < 8; i++) {
        int gm = m0 + ty * 8 + i;
        if (gm >= M) continue;
#pragma unroll
        for (int j = 0; j < 8; j++) {
            int gn = n0 + tx * 8 + j;
            if (gn >= N) continue;
            float v = acc[i][j];
            if (bias)   v += bias[gn];
            if (doRelu) v = fmaxf(v, 0.f);
            if (cscale) v *= cscale[gn];
            Cb[(long long)gm * ldc + gn] = v;
        }
    }
}

// ---------------------------------------------------------------------------
// Masked row softmax over L2 (in place). One block per (b,l) row.
// ---------------------------------------------------------------------------
__global__ void softmax_kernel(float* __restrict__ S,
                               const unsigned char* __restrict__ mask) {
    int row = blockIdx.x;               // b*L1 + l
    int b = row / LL1;
    float* s = S + (long long)row * LL2;
    const unsigned char* m = mask + (long long)b * LL2;
    int t = threadIdx.x;                // 256 threads

    __shared__ float red[256];

    float mx = -3.402823466e38f;
    for (int i = t; i < LL2; i += 256) {
        float v = m[i] ? -3.402823466e38f : s[i];
        s[i] = v;
        mx = fmaxf(mx, v);
    }
    red[t] = mx; __syncthreads();
    for (int o = 128; o > 0; o >>= 1) {
        if (t < o) red[t] = fmaxf(red[t], red[t + o]);
        __syncthreads();
    }
    mx = red[0]; __syncthreads();

    float sum = 0.f;
    for (int i = t; i < LL2; i += 256) {
        float e = __expf(s[i] - mx);
        s[i] = e;
        sum += e;
    }
    red[t] = sum; __syncthreads();
    for (int o = 128; o > 0; o >>= 1) {
        if (t < o) red[t] += red[t + o];
        __syncthreads();
    }
    float inv = 1.f / red[0];
    for (int i = t; i < LL2; i += 256) s[i] *= inv;
}

// ---------------------------------------------------------------------------
// BiLSTM recurrence. 32 blocks: block = dir*16 + b. 512 threads = 1 gate each.
// g_in precomputed (bias included). h broadcast via smem; c in registers of
// threads 0..127. Output: out[(b*L1+l)*256 + dir*128 + j]
// ---------------------------------------------------------------------------
__global__ __launch_bounds__(512, 1)
void lstm_kernel(const float* __restrict__ gin_f, const float* __restrict__ gin_b,
                 const float* __restrict__ Whh_f, const float* __restrict__ Whh_b,
                 float* __restrict__ out) {
    int blk = blockIdx.x;
    int dir = blk >> 4;
    int b = blk & 15;
    const float* gin = dir ? gin_b : gin_f;
    const float* W = dir ? Whh_b : Whh_f;
    int t = threadIdx.x;   // gate id 0..511

    __shared__ float h_s[128];
    __shared__ float z_s[512];
    if (t < 128) h_s[t] = 0.f;
    float c = 0.f;
    const float4* w4 = reinterpret_cast<const float4*>(W + t * HH);
    __syncthreads();

    for (int step = 0; step < LL1; step++) {
        int l = dir ? (LL1 - 1 - step) : step;
        float acc = gin[((long long)(b * LL1 + l)) * GATES + t];
#pragma unroll 8
        for (int k = 0; k < HH / 4; k++) {
            float4 w = __ldg(&w4[k]);
            float4 h = *reinterpret_cast<const float4*>(&h_s[k * 4]);
            acc += w.x * h.x + w.y * h.y + w.z * h.z + w.w * h.w;
        }
        z_s[t] = acc;
        __syncthreads();
        if (t < 128) {
            float zi = z_s[t], zf = z_s[128 + t], zg = z_s[256 + t], zo = z_s[384 + t];
            float ig = 1.f / (1.f + expf(-zi));
            float fg = 1.f / (1.f + expf(-zf));
            float gg = tanhf(zg);
            float og = 1.f / (1.f + expf(-zo));
            c = fg * c + ig * gg;
            float h = og * tanhf(c);
            h_s[t] = h;
            out[((long long)(b * LL1 + l)) * 256 + dir * HH + t] = h;
        }
        __syncthreads();
    }
}

// ---------------------------------------------------------------------------
// Launch orchestration
// ---------------------------------------------------------------------------
static float* symaddr(const void* sym) {
    void* p = nullptr;
    cudaGetSymbolAddress(&p, sym);
    return (float*)p;
}

extern "C" void kernel_launch(void* const* d_in, const int* in_sizes, int n_in,
                              void* d_out, int out_size) {
    const float* x1_word = (const float*)d_in[0];
    const float* x1_a0   = (const float*)d_in[1];
    const float* x1_a1   = (const float*)d_in[2];
    const float* x2_word = (const float*)d_in[3];
    const float* x2_a0   = (const float*)d_in[4];
    const float* x2_a1   = (const float*)d_in[5];
    const float* x2_a2   = (const float*)d_in[6];
    // d_in[7] = x1_mask (unused by reference)
    const unsigned char* x2_mask = (const unsigned char*)d_in[8];
    const float* W_attn  = (const float*)d_in[9];
    const float* v_attn  = (const float*)d_in[10];
    const float* Wih_f   = (const float*)d_in[11];
    const float* Whh_f   = (const float*)d_in[12];
    const float* b_f     = (const float*)d_in[13];
    const float* Wih_b   = (const float*)d_in[14];
    const float* Whh_b   = (const float*)d_in[15];
    const float* b_b     = (const float*)d_in[16];
    float* out = (float*)d_out;

    float* x1_att = symaddr(g_x1_att);
    float* x2_att = symaddr(g_x2_att);
    float* r1     = symaddr(g_r1);
    float* r2     = symaddr(g_r2);
    float* scores = symaddr(g_scores);
    float* x1cat  = symaddr(g_x1cat);
    float* gin_f  = symaddr(g_gin_f);
    float* gin_b  = symaddr(g_gin_b);

    const float* x2_list[3] = {x2_a0, x2_a1, x2_a2};

    // 1) concat inputs
    {
        int total = ROWS1 * ATT_IN;
        concat_att_kernel<<<(total + 255) / 256, 256>>>(x1_word, x1_a0, x1_a1, x1_att, ROWS1);
        concat_att_kernel<<<(total + 255) / 256, 256>>>(x2_word, x2_a0, x2_a1, x2_att, ROWS2);
        int t2 = ROWS1 * 2 * AH;
        init_cat_kernel<<<(t2 + 255) / 256, 256>>>(x1_a0, x1_a1, x1cat, ROWS1);
    }

    // 2) three attention modules
    for (int i = 0; i < 3; i++) {
        const float* Wi = W_attn + (long long)i * ATT * ATT_IN;
        const float* vi = v_attn + (long long)i * ATT;

        {   // r1 = relu(x1_att @ Wi^T)  [8192,250]
            dim3 grid((ATT + 127) / 128, (ROWS1 + 127) / 128, 1);
            gemm_kernel<true><<<grid, 256>>>(x1_att, Wi, nullptr, nullptr, r1,
                                             ROWS1, ATT, ATT_IN, ATT, 0, 0, 0, 1);
        }
        {   // r2 = relu(x2_att @ Wi^T) * v  [8192,250]
            dim3 grid((ATT + 127) / 128, (ROWS2 + 127) / 128, 1);
            gemm_kernel<true><<<grid, 256>>>(x2_att, Wi, nullptr, vi, r2,
                                             ROWS2, ATT, ATT_IN, ATT, 0, 0, 0, 1);
        }
        {   // scores[b] = r1_b @ r2_b^T  [512,512] x16
            dim3 grid((LL2 + 127) / 128, (LL1 + 127) / 128, BB);
            gemm_kernel<true><<<grid, 256>>>(r1, r2, nullptr, nullptr, scores,
                                             LL1, LL2, ATT, LL2,
                                             (long long)LL1 * ATT, (long long)LL2 * ATT,
                                             (long long)LL1 * LL2, 0);
        }
        // masked softmax over last dim
        softmax_kernel<<<ROWS1, 256>>>(scores, x2_mask);
        {   // piece_i = alpha @ x2_list[i] -> x1cat cols [512 + 256*i)
            dim3 grid((AH + 127) / 128, (LL1 + 127) / 128, BB);
            gemm_kernel<false><<<grid, 256>>>(scores, x2_list[i], nullptr, nullptr,
                                              x1cat + 2 * AH + i * AH,
                                              LL1, AH, LL2, RNN_IN,
                                              (long long)LL1 * LL2, (long long)LL2 * AH,
                                              (long long)LL1 * RNN_IN, 0);
        }
    }

    // 3) LSTM input gates: g_in = x1cat @ Wih^T + b   [8192,512] per direction
    {
        dim3 grid((GATES + 127) / 128, (ROWS1 + 127) / 128, 1);
        gemm_kernel<true><<<grid, 256>>>(x1cat, Wih_f, b_f, nullptr, gin_f,
                                         ROWS1, GATES, RNN_IN, GATES, 0, 0, 0, 0);
        gemm_kernel<true><<<grid, 256>>>(x1cat, Wih_b, b_b, nullptr, gin_b,
                                         ROWS1, GATES, RNN_IN, GATES, 0, 0, 0, 0);
    }

    // 4) recurrence (fwd + bwd in parallel across 32 blocks)
    lstm_kernel<<<32, 512>>>(gin_f, gin_b, Whh_f, Whh_b, out);
}

// round 3
// speedup vs baseline: 1.1971x; 1.1971x over previous
#include <cuda_runtime.h>
#include <math.h>

// ---------------------------------------------------------------------------
// Problem constants
// ---------------------------------------------------------------------------
#define BB   16
#define LL1  512
#define LL2  512
#define EMB  300
#define AH   256
#define ATT  250
#define HH   128
#define ATT_IN 812
#define RNN_IN 1280
#define GATES  512
#define ROWS1 (BB*LL1)
#define ROWS2 (BB*LL2)

// ---------------------------------------------------------------------------
// Scratch
// ---------------------------------------------------------------------------
__device__ float g_x1_att[ROWS1 * ATT_IN];
__device__ float g_x2_att[ROWS2 * ATT_IN];
__device__ float g_r1[ROWS1 * ATT];
__device__ float g_r2[ROWS2 * ATT];
__device__ float g_scores[ROWS1 * LL2];
__device__ float g_x1cat[ROWS1 * RNN_IN];
__device__ float g_gin_f[ROWS1 * GATES];
__device__ float g_gin_b[ROWS1 * GATES];
__device__ float g_x2T[3][BB * AH * LL2];   // x2_abstr transposed to [B][AH][L2]

// ---------------------------------------------------------------------------
// Helpers
// ---------------------------------------------------------------------------
__device__ __forceinline__ float f2tf32(float x) {
    float r; asm("cvt.rna.tf32.f32 %0, %1;" : "=f"(r) : "f"(x)); return r;
}

__device__ __forceinline__ void mma_tf32(float c[4],
                                         float a0, float a1, float a2, float a3,
                                         float b0, float b1) {
    asm("mma.sync.aligned.m16n8k8.row.col.f32.tf32.tf32.f32 "
        "{%0,%1,%2,%3},{%4,%5,%6,%7},{%8,%9},{%0,%1,%2,%3};"
        : "+f"(c[0]), "+f"(c[1]), "+f"(c[2]), "+f"(c[3])
        : "r"(__float_as_uint(a0)), "r"(__float_as_uint(a1)),
          "r"(__float_as_uint(a2)), "r"(__float_as_uint(a3)),
          "r"(__float_as_uint(b0)), "r"(__float_as_uint(b1)));
}

#define PLANE (128 * 36)

// ---------------------------------------------------------------------------
// Concat kernels
// ---------------------------------------------------------------------------
__global__ void concat_att_kernel(const float* __restrict__ w,
                                  const float* __restrict__ a0,
                                  const float* __restrict__ a1,
                                  float* __restrict__ out, int rows) {
    int idx = blockIdx.x * blockDim.x + threadIdx.x;
    int total = rows * ATT_IN;
    if (idx >= total) return;
    int r = idx / ATT_IN;
    int d = idx - r * ATT_IN;
    float v;
    if (d < EMB)            v = w[r * EMB + d];
    else if (d < EMB + AH)  v = a0[r * AH + (d - EMB)];
    else                    v = a1[r * AH + (d - EMB - AH)];
    out[idx] = v;
}

__global__ void init_cat_kernel(const float* __restrict__ a0,
                                const float* __restrict__ a1,
                                float* __restrict__ cat, int rows) {
    int idx = blockIdx.x * blockDim.x + threadIdx.x;
    int total = rows * (2 * AH);
    if (idx >= total) return;
    int r = idx / (2 * AH);
    int d = idx - r * (2 * AH);
    float v = (d < AH) ? a0[r * AH + d] : a1[r * AH + (d - AH)];
    cat[(long long)r * RNN_IN + d] = v;
}

// Transpose [B][L2][AH] -> [B][AH][L2]
__global__ void transpose_kernel(const float* __restrict__ in,
                                 float* __restrict__ out) {
    __shared__ float tile[32][33];
    int b = blockIdx.z;
    int mBase = blockIdx.x * 32, dBase = blockIdx.y * 32;
    const float* ib = in + (long long)b * LL2 * AH;
    float* ob = out + (long long)b * AH * LL2;
    int tx = threadIdx.x, ty = threadIdx.y;   // 32 x 8
#pragma unroll
    for (int i = 0; i < 32; i += 8)
        tile[ty + i][tx] = ib[(long long)(mBase + ty + i) * AH + dBase + tx];
    __syncthreads();
#pragma unroll
    for (int i = 0; i < 32; i += 8)
        ob[(long long)(dBase + ty + i) * LL2 + mBase + tx] = tile[tx][ty + i];
}

// ---------------------------------------------------------------------------
// Tensor-core TF32 GEMM: C = epilogue(A @ B^T), A [M,K], B [N,K] row-major.
// SPLIT=1: plain tf32. SPLIT=2: tf32-3x (hi/lo compensated, ~fp32 accuracy).
// Tile 128x128x32, 256 threads (8 warps in 2x4), warp tile 64x32 via m16n8k8.
// Smem K-permuted (k' = (k%4)*8 + k/4) so fragment loads are LDS.128,
// conflict-free with row stride 36 floats.
// ---------------------------------------------------------------------------
template <int SPLIT>
__global__ __launch_bounds__(256, 1)
void gemm_tc(const float* __restrict__ A, const float* __restrict__ B,
             const float* __restrict__ bias, const float* __restrict__ cscale,
             float* __restrict__ C,
             int M, int N, int K, int ldc,
             long long strA, long long strB, long long strC, int doRelu) {
    extern __shared__ float smbuf[];
    float* sA = smbuf;                       // [stage][SPLIT][PLANE]
    float* sB = smbuf + 2 * SPLIT * PLANE;

    const float* Ab = A + (long long)blockIdx.z * strA;
    const float* Bb = B + (long long)blockIdx.z * strB;
    float* Cb = C + (long long)blockIdx.z * strC;

    const int m0 = blockIdx.y * 128;
    const int n0 = blockIdx.x * 128;
    const int t = threadIdx.x;
    const int wid = t >> 5, lane = t & 31;
    const int wm = wid >> 2, wn = wid & 3;       // 2 x 4 warp grid
    const int grp = lane >> 2, qid = lane & 3;

    const int lrow = t >> 5;                     // 0..7 (loader row group)
    const int lcol = t & 31;                     // 0..31 (loader k)
    const int kperm = ((lcol & 3) << 3) + (lcol >> 2);

    float acc[4][4][4];
#pragma unroll
    for (int i = 0; i < 4; i++)
#pragma unroll
        for (int j = 0; j < 4; j++)
#pragma unroll
            for (int e = 0; e < 4; e++) acc[i][j][e] = 0.f;

    float rA[16], rB[16];

    auto LOADG = [&](int k0) {
        int gk = k0 + lcol;
        bool kok = (gk < K);
#pragma unroll
        for (int i = 0; i < 16; i++) {
            int gr = lrow + i * 8;
            int gm = m0 + gr;
            rA[i] = (kok && gm < M) ? Ab[(long long)gm * K + gk] : 0.f;
            int gn = n0 + gr;
            rB[i] = (kok && gn < N) ? Bb[(long long)gn * K + gk] : 0.f;
        }
    };

    auto STS = [&](int stage) {
        float* pa = sA + stage * SPLIT * PLANE;
        float* pb = sB + stage * SPLIT * PLANE;
#pragma unroll
        for (int i = 0; i < 16; i++) {
            int off = (lrow + i * 8) * 36 + kperm;
            float hia = f2tf32(rA[i]);
            pa[off] = hia;
            if (SPLIT == 2) pa[PLANE + off] = f2tf32(rA[i] - hia);
            float hib = f2tf32(rB[i]);
            pb[off] = hib;
            if (SPLIT == 2) pb[PLANE + off] = f2tf32(rB[i] - hib);
        }
    };

#define MMABLK(A0, A1, BV)                                                    \
    _Pragma("unroll")                                                         \
    for (int mt = 0; mt < 4; mt++) {                                          \
        _Pragma("unroll")                                                     \
        for (int nt = 0; nt < 4; nt++) {                                      \
            mma_tf32(acc[mt][nt], (A0)[mt].x, (A1)[mt].x, (A0)[mt].y,         \
                     (A1)[mt].y, (BV)[nt].x, (BV)[nt].y);                     \
            mma_tf32(acc[mt][nt], (A0)[mt].z, (A1)[mt].z, (A0)[mt].w,         \
                     (A1)[mt].w, (BV)[nt].z, (BV)[nt].w);                     \
        }                                                                     \
    }

    auto COMPUTE = [&](int stage) {
        float* pa = sA + stage * SPLIT * PLANE;
        float* pb = sB + stage * SPLIT * PLANE;
#pragma unroll
        for (int h = 0; h < 2; h++) {
            float4 a0[4], a1[4], bv[4];
#pragma unroll
            for (int mt = 0; mt < 4; mt++) {
                int r = wm * 64 + mt * 16 + grp;
                a0[mt] = *(const float4*)&pa[r * 36 + qid * 8 + h * 4];
                a1[mt] = *(const float4*)&pa[(r + 8) * 36 + qid * 8 + h * 4];
            }
#pragma unroll
            for (int nt = 0; nt < 4; nt++) {
                int r = wn * 32 + nt * 8 + grp;
                bv[nt] = *(const float4*)&pb[r * 36 + qid * 8 + h * 4];
            }
            MMABLK(a0, a1, bv)
            if (SPLIT == 2) {
                float4 bl[4];
#pragma unroll
                for (int nt = 0; nt < 4; nt++) {
                    int r = wn * 32 + nt * 8 + grp;
                    bl[nt] = *(const float4*)&pb[PLANE + r * 36 + qid * 8 + h * 4];
                }
                MMABLK(a0, a1, bl)      // hi * lo
#pragma unroll
                for (int mt = 0; mt < 4; mt++) {
                    int r = wm * 64 + mt * 16 + grp;
                    a0[mt] = *(const float4*)&pa[PLANE + r * 36 + qid * 8 + h * 4];
                    a1[mt] = *(const float4*)&pa[PLANE + (r + 8) * 36 + qid * 8 + h * 4];
                }
                MMABLK(a0, a1, bv)      // lo * hi
            }
        }
    };

    int nk = (K + 31) >> 5;
    LOADG(0);
    STS(0);
    __syncthreads();
    int cur = 0;
    for (int kt = 0; kt < nk; kt++) {
        if (kt + 1 < nk) LOADG((kt + 1) << 5);
        COMPUTE(cur);
        if (kt + 1 < nk) {
            STS(cur ^ 1);
            __syncthreads();
            cur ^= 1;
        }
    }

    // Epilogue
#pragma unroll
    for (int mt = 0; mt < 4; mt++) {
        int r0 = m0 + wm * 64 + mt * 16 + grp;
#pragma unroll
        for (int nt = 0; nt < 4; nt++) {
            int cn = n0 + wn * 32 + nt * 8 + qid * 2;
            float* c = acc[mt][nt];
#pragma unroll
            for (int e = 0; e < 4; e++) {
                int gm = r0 + (e >= 2 ? 8 : 0);
                int gn = cn + (e & 1);
                if (gm >= M || gn >= N) continue;
                float v = c[e];
                if (bias)   v += bias[gn];
                if (doRelu) v = fmaxf(v, 0.f);
                if (cscale) v *= cscale[gn];
                Cb[(long long)gm * ldc + gn] = v;
            }
        }
    }
#undef MMABLK
}

// ---------------------------------------------------------------------------
// Masked row softmax over L2 (in place)
// ---------------------------------------------------------------------------
__global__ void softmax_kernel(float* __restrict__ S,
                               const unsigned char* __restrict__ mask) {
    int row = blockIdx.x;
    int b = row / LL1;
    float* s = S + (long long)row * LL2;
    const unsigned char* m = mask + (long long)b * LL2;
    int t = threadIdx.x;

    __shared__ float red[256];

    float mx = -3.402823466e38f;
    for (int i = t; i < LL2; i += 256) {
        float v = m[i] ? -3.402823466e38f : s[i];
        s[i] = v;
        mx = fmaxf(mx, v);
    }
    red[t] = mx; __syncthreads();
    for (int o = 128; o > 0; o >>= 1) {
        if (t < o) red[t] = fmaxf(red[t], red[t + o]);
        __syncthreads();
    }
    mx = red[0]; __syncthreads();

    float sum = 0.f;
    for (int i = t; i < LL2; i += 256) {
        float e = __expf(s[i] - mx);
        s[i] = e;
        sum += e;
    }
    red[t] = sum; __syncthreads();
    for (int o = 128; o > 0; o >>= 1) {
        if (t < o) red[t] += red[t + o];
        __syncthreads();
    }
    float inv = 1.f / red[0];
    for (int i = t; i < LL2; i += 256) s[i] *= inv;
}

// ---------------------------------------------------------------------------
// BiLSTM recurrence
// ---------------------------------------------------------------------------
__global__ __launch_bounds__(512, 1)
void lstm_kernel(const float* __restrict__ gin_f, const float* __restrict__ gin_b,
                 const float* __restrict__ Whh_f, const float* __restrict__ Whh_b,
                 float* __restrict__ out) {
    int blk = blockIdx.x;
    int dir = blk >> 4;
    int b = blk & 15;
    const float* gin = dir ? gin_b : gin_f;
    const float* W = dir ? Whh_b : Whh_f;
    int t = threadIdx.x;

    __shared__ float h_s[128];
    __shared__ float z_s[512];
    if (t < 128) h_s[t] = 0.f;
    float c = 0.f;
    const float4* w4 = reinterpret_cast<const float4*>(W + t * HH);
    __syncthreads();

    for (int step = 0; step < LL1; step++) {
        int l = dir ? (LL1 - 1 - step) : step;
        float acc = gin[((long long)(b * LL1 + l)) * GATES + t];
#pragma unroll 8
        for (int k = 0; k < HH / 4; k++) {
            float4 w = __ldg(&w4[k]);
            float4 h = *reinterpret_cast<const float4*>(&h_s[k * 4]);
            acc += w.x * h.x + w.y * h.y + w.z * h.z + w.w * h.w;
        }
        z_s[t] = acc;
        __syncthreads();
        if (t < 128) {
            float zi = z_s[t], zf = z_s[128 + t], zg = z_s[256 + t], zo = z_s[384 + t];
            float ig = 1.f / (1.f + expf(-zi));
            float fg = 1.f / (1.f + expf(-zf));
            float gg = tanhf(zg);
            float og = 1.f / (1.f + expf(-zo));
            c = fg * c + ig * gg;
            float h = og * tanhf(c);
            h_s[t] = h;
            out[((long long)(b * LL1 + l)) * 256 + dir * HH + t] = h;
        }
        __syncthreads();
    }
}

// ---------------------------------------------------------------------------
// Launch orchestration
// ---------------------------------------------------------------------------
static float* symaddr(const void* sym) {
    void* p = nullptr;
    cudaGetSymbolAddress(&p, sym);
    return (float*)p;
}

extern "C" void kernel_launch(void* const* d_in, const int* in_sizes, int n_in,
                              void* d_out, int out_size) {
    const float* x1_word = (const float*)d_in[0];
    const float* x1_a0   = (const float*)d_in[1];
    const float* x1_a1   = (const float*)d_in[2];
    const float* x2_word = (const float*)d_in[3];
    const float* x2_a0   = (const float*)d_in[4];
    const float* x2_a1   = (const float*)d_in[5];
    const float* x2_a2   = (const float*)d_in[6];
    const unsigned char* x2_mask = (const unsigned char*)d_in[8];
    const float* W_attn  = (const float*)d_in[9];
    const float* v_attn  = (const float*)d_in[10];
    const float* Wih_f   = (const float*)d_in[11];
    const float* Whh_f   = (const float*)d_in[12];
    const float* b_f     = (const float*)d_in[13];
    const float* Wih_b   = (const float*)d_in[14];
    const float* Whh_b   = (const float*)d_in[15];
    const float* b_b     = (const float*)d_in[16];
    float* out = (float*)d_out;

    float* x1_att = symaddr(g_x1_att);
    float* x2_att = symaddr(g_x2_att);
    float* r1     = symaddr(g_r1);
    float* r2     = symaddr(g_r2);
    float* scores = symaddr(g_scores);
    float* x1cat  = symaddr(g_x1cat);
    float* gin_f  = symaddr(g_gin_f);
    float* gin_b  = symaddr(g_gin_b);
    float* x2T    = symaddr(g_x2T);

    const size_t SMEM1 = 2 * 1 * 2 * (size_t)PLANE * 4;   //  72 KB
    const size_t SMEM2 = 2 * 2 * 2 * (size_t)PLANE * 4;   // 144 KB
    cudaFuncSetAttribute(gemm_tc<1>, cudaFuncAttributeMaxDynamicSharedMemorySize, (int)SMEM1);
    cudaFuncSetAttribute(gemm_tc<2>, cudaFuncAttributeMaxDynamicSharedMemorySize, (int)SMEM2);

    const float* x2_list[3] = {x2_a0, x2_a1, x2_a2};

    // 1) concat + transposes
    {
        int total = ROWS1 * ATT_IN;
        concat_att_kernel<<<(total + 255) / 256, 256>>>(x1_word, x1_a0, x1_a1, x1_att, ROWS1);
        concat_att_kernel<<<(total + 255) / 256, 256>>>(x2_word, x2_a0, x2_a1, x2_att, ROWS2);
        int t2 = ROWS1 * 2 * AH;
        init_cat_kernel<<<(t2 + 255) / 256, 256>>>(x1_a0, x1_a1, x1cat, ROWS1);
        dim3 tg(LL2 / 32, AH / 32, BB), tb(32, 8);
        for (int i = 0; i < 3; i++)
            transpose_kernel<<<tg, tb>>>(x2_list[i], x2T + (size_t)i * BB * AH * LL2);
    }

    // 2) three attention modules
    for (int i = 0; i < 3; i++) {
        const float* Wi = W_attn + (long long)i * ATT * ATT_IN;
        const float* vi = v_attn + (long long)i * ATT;

        {   // r1 = relu(x1_att @ Wi^T)   (tf32-3x)
            dim3 grid((ATT + 127) / 128, (ROWS1 + 127) / 128, 1);
            gemm_tc<2><<<grid, 256, SMEM2>>>(x1_att, Wi, nullptr, nullptr, r1,
                                             ROWS1, ATT, ATT_IN, ATT, 0, 0, 0, 1);
        }
        {   // r2 = relu(x2_att @ Wi^T) * v   (tf32-3x)
            dim3 grid((ATT + 127) / 128, (ROWS2 + 127) / 128, 1);
            gemm_tc<2><<<grid, 256, SMEM2>>>(x2_att, Wi, nullptr, vi, r2,
                                             ROWS2, ATT, ATT_IN, ATT, 0, 0, 0, 1);
        }
        {   // scores[b] = r1_b @ r2_b^T   (tf32-3x, batched)
            dim3 grid((LL2 + 127) / 128, (LL1 + 127) / 128, BB);
            gemm_tc<2><<<grid, 256, SMEM2>>>(r1, r2, nullptr, nullptr, scores,
                                             LL1, LL2, ATT, LL2,
                                             (long long)LL1 * ATT, (long long)LL2 * ATT,
                                             (long long)LL1 * LL2, 0);
        }
        softmax_kernel<<<ROWS1, 256>>>(scores, x2_mask);
        {   // piece_i = alpha @ x2_list[i]  (tf32-1x, B pre-transposed)
            dim3 grid((AH + 127) / 128, (LL1 + 127) / 128, BB);
            gemm_tc<1><<<grid, 256, SMEM1>>>(scores, x2T + (size_t)i * BB * AH * LL2,
                                             nullptr, nullptr,
                                             x1cat + 2 * AH + i * AH,
                                             LL1, AH, LL2, RNN_IN,
                                             (long long)LL1 * LL2, (long long)AH * LL2,
                                             (long long)LL1 * RNN_IN, 0);
        }
    }

    // 3) LSTM input gates (tf32-1x)
    {
        dim3 grid((GATES + 127) / 128, (ROWS1 + 127) / 128, 1);
        gemm_tc<1><<<grid, 256, SMEM1>>>(x1cat, Wih_f, b_f, nullptr, gin_f,
                                         ROWS1, GATES, RNN_IN, GATES, 0, 0, 0, 0);
        gemm_tc<1><<<grid, 256, SMEM1>>>(x1cat, Wih_b, b_b, nullptr, gin_b,
                                         ROWS1, GATES, RNN_IN, GATES, 0, 0, 0, 0);
    }

    // 4) recurrence
    lstm_kernel<<<32, 512>>>(gin_f, gin_b, Whh_f, Whh_b, out);
}

// round 7
// speedup vs baseline: 1.2088x; 1.0098x over previous
#include <cuda_runtime.h>
#include <cuda_bf16.h>
#include <math.h>
#include <cstdint>

typedef unsigned short u16;

// ---------------------------------------------------------------------------
// Problem constants
// ---------------------------------------------------------------------------
#define BB   16
#define LL   512
#define EMB  300
#define AH   256
#define ATT  250
#define HH   128
#define ATT_IN 812
#define RNN_IN 1280
#define GATES  512
#define ROWS (BB*LL)        // 8192

#define K1   832            // padded ATT_IN
#define K1E  (6*K1)         // 4992  (split-3 expanded)
#define KRE  (6*256)        // 1536  (scores K, split-3 expanded, ATT->256 pad)
#define KSE  (3*512)        // 1536  (alphaV K, split-2 expanded)
#define KCE  (3*RNN_IN)     // 3840  (gin K, split-2 expanded)

// ---------------------------------------------------------------------------
// Scratch (static __device__; no allocations allowed)
// ---------------------------------------------------------------------------
__device__ u16  g_x1e[ROWS * K1E];               // x1_att A-side split3
__device__ u16  g_x2e[ROWS * K1E];               // x2_att A-side split3
__device__ u16  g_We[768 * K1E];                 // W_attn (3 modules) B-side split3
__device__ u16  g_r1e[3ll * ROWS * KRE];         // r1 A-side split3 [module][8192][1536]
__device__ u16  g_r2e[3ll * ROWS * KRE];         // r2 B-side split3
__device__ u16  g_ae [3ll * ROWS * KSE];         // alpha A-side split2
__device__ u16  g_x2Te[3ll * BB * AH * KSE];     // x2T B-side split2 [m][b][256][1536]
__device__ u16  g_x1ce[(long long)ROWS * KCE];   // x1cat A-side split2 [8192][3840]
__device__ u16  g_Wihe[2ll * GATES * KCE];       // Wih B-side split2 [dir][512][3840]
__device__ float g_scores[3ll * BB * LL * LL];   // [m][b][512][512]
__device__ float g_gin[2ll * ROWS * GATES];      // [dir][8192][512]

// ---------------------------------------------------------------------------
// Helpers
// ---------------------------------------------------------------------------
__device__ __forceinline__ uint32_t smem_to_u32(const void* p) {
    uint32_t a;
    asm("{ .reg .u64 t; cvta.to.shared.u64 t, %1; cvt.u32.u64 %0, t; }"
        : "=r"(a) : "l"(p));
    return a;
}

__device__ __forceinline__ void cpasync16(uint32_t dst, const void* src) {
    asm volatile("cp.async.cg.shared.global [%0], [%1], 16;"
                 :: "r"(dst), "l"(src));
}
#define CP_COMMIT() asm volatile("cp.async.commit_group;")
#define CP_WAIT2()  asm volatile("cp.async.wait_group 2;")

__device__ __forceinline__ void ldsm4(uint32_t& r0, uint32_t& r1,
                                      uint32_t& r2, uint32_t& r3, uint32_t a) {
    asm volatile("ldmatrix.sync.aligned.m8n8.x4.shared.b16 {%0,%1,%2,%3}, [%4];"
                 : "=r"(r0), "=r"(r1), "=r"(r2), "=r"(r3) : "r"(a));
}

__device__ __forceinline__ void mma_bf16(float* c, const uint32_t* a,
                                         const uint32_t* b) {
    asm volatile(
        "mma.sync.aligned.m16n8k16.row.col.f32.bf16.bf16.f32 "
        "{%0,%1,%2,%3},{%4,%5,%6,%7},{%8,%9},{%0,%1,%2,%3};"
        : "+f"(c[0]), "+f"(c[1]), "+f"(c[2]), "+f"(c[3])
        : "r"(a[0]), "r"(a[1]), "r"(a[2]), "r"(a[3]), "r"(b[0]), "r"(b[1]));
}

__device__ __forceinline__ u16 bfu(float x) {
    __nv_bfloat16 h = __float2bfloat16(x);
    return *reinterpret_cast<u16*>(&h);
}
__device__ __forceinline__ float ubf(u16 u) {
    __nv_bfloat16 h = *reinterpret_cast<__nv_bfloat16*>(&u);
    return __bfloat162float(h);
}
__device__ __forceinline__ void split3u(float x, u16& a, u16& b, u16& c) {
    a = bfu(x); float r = x - ubf(a);
    b = bfu(r); r -= ubf(b);
    c = bfu(r);
}
__device__ __forceinline__ void split2u(float x, u16& a, u16& b) {
    a = bfu(x); b = bfu(x - ubf(a));
}

// ---------------------------------------------------------------------------
// Prep kernels (write K-expanded bf16 planes)
// ---------------------------------------------------------------------------
// A-side split3 segs planes {0,0,1,0,1,2}; B-side {0,1,0,2,1,0}
// A-side split2 {0,0,1}; B-side {0,1,0}

__global__ void prep_x3(const float* __restrict__ w, const float* __restrict__ a0,
                        const float* __restrict__ a1, u16* __restrict__ out) {
    long long idx = (long long)blockIdx.x * blockDim.x + threadIdx.x;
    if (idx >= (long long)ROWS * K1) return;
    int r = (int)(idx / K1), k = (int)(idx % K1);
    float x = 0.f;
    if (k < EMB)            x = w[r * EMB + k];
    else if (k < EMB + AH)  x = a0[r * AH + (k - EMB)];
    else if (k < ATT_IN)    x = a1[r * AH + (k - EMB - AH)];
    u16 p[3]; split3u(x, p[0], p[1], p[2]);
    u16* o = out + (long long)r * K1E + k;
    o[0*K1] = p[0]; o[1*K1] = p[0]; o[2*K1] = p[1];
    o[3*K1] = p[0]; o[4*K1] = p[1]; o[5*K1] = p[2];
}

__global__ void prep_W3(const float* __restrict__ W, u16* __restrict__ out) {
    long long idx = (long long)blockIdx.x * blockDim.x + threadIdx.x;
    if (idx >= (long long)768 * K1) return;
    int row = (int)(idx / K1), k = (int)(idx % K1);
    int m = row >> 8, r = row & 255;
    float x = (r < ATT && k < ATT_IN) ? W[((long long)m * ATT + r) * ATT_IN + k] : 0.f;
    u16 p[3]; split3u(x, p[0], p[1], p[2]);
    u16* o = out + (long long)row * K1E + k;
    o[0*K1] = p[0]; o[1*K1] = p[1]; o[2*K1] = p[0];
    o[3*K1] = p[2]; o[4*K1] = p[1]; o[5*K1] = p[0];
}

__global__ void prep_Wih2(const float* __restrict__ Wf, const float* __restrict__ Wb,
                          u16* __restrict__ out) {
    long long idx = (long long)blockIdx.x * blockDim.x + threadIdx.x;
    if (idx >= (long long)2 * GATES * RNN_IN) return;
    int row = (int)(idx / RNN_IN), k = (int)(idx % RNN_IN);
    int dir = row >> 9, r = row & 511;
    float x = dir ? Wb[(long long)r * RNN_IN + k] : Wf[(long long)r * RNN_IN + k];
    u16 p[2]; split2u(x, p[0], p[1]);
    u16* o = out + (long long)row * KCE + k;
    o[0*RNN_IN] = p[0]; o[1*RNN_IN] = p[1]; o[2*RNN_IN] = p[0];
}

__global__ void init_cat2(const float* __restrict__ a0, const float* __restrict__ a1,
                          u16* __restrict__ out) {
    long long idx = (long long)blockIdx.x * blockDim.x + threadIdx.x;
    if (idx >= (long long)ROWS * 2 * AH) return;
    int r = (int)(idx / (2 * AH)), d = (int)(idx % (2 * AH));
    float x = (d < AH) ? a0[r * AH + d] : a1[r * AH + (d - AH)];
    u16 p[2]; split2u(x, p[0], p[1]);
    u16* o = out + (long long)r * KCE + d;
    o[0*RNN_IN] = p[0]; o[1*RNN_IN] = p[0]; o[2*RNN_IN] = p[1];
}

// x2_abstr [16][512][256] -> x2Te[m] [16][256][1536] B-side split2
__global__ void transpose2(const float* __restrict__ in, u16* __restrict__ out) {
    __shared__ float tile[32][33];
    int b = blockIdx.z;
    int lBase = blockIdx.x * 32, dBase = blockIdx.y * 32;
    const float* ib = in + (long long)b * LL * AH;
    int tx = threadIdx.x, ty = threadIdx.y;   // 32 x 8
#pragma unroll
    for (int i = 0; i < 32; i += 8)
        tile[ty + i][tx] = ib[(long long)(lBase + ty + i) * AH + dBase + tx];
    __syncthreads();
    long long ob = (long long)b * AH * KSE;
#pragma unroll
    for (int i = 0; i < 32; i += 8) {
        float v = tile[tx][ty + i];
        u16 p[2]; split2u(v, p[0], p[1]);
        u16* o = out + ob + (long long)(dBase + ty + i) * KSE + (lBase + tx);
        o[0*LL] = p[0]; o[1*LL] = p[1]; o[2*LL] = p[0];
    }
}

// ---------------------------------------------------------------------------
// bf16 NT GEMM (mma.sync m16n8k16): C = epi(A @ B^T)
// Tile 128x128x32, 8 warps (2x4), cp.async 4-stage, 2 CTAs/SM.
// outSplit: 0 = fp32 (+bias), 2/3 = plane-expanded bf16 output.
// ---------------------------------------------------------------------------
__global__ __launch_bounds__(256, 2)
void gemm_bf16(const u16* __restrict__ A, const u16* __restrict__ Bm,
               long long aHi, long long aLo, long long bHi, long long bLo,
               float* __restrict__ outF, long long cHi, long long cLo, int ldc,
               const float* __restrict__ bias, const float* __restrict__ vsc,
               u16* __restrict__ outP, long long pHi, long long pLo, long long pCo,
               int ldp, int segW, long long modStride, int colShift, int colMask,
               int outSplit, int side, int doRelu, int Kp) {
    extern __shared__ char smem[];
    const uint32_t sb = smem_to_u32(smem);
    const int t = threadIdx.x;
    const int lane = t & 31, wid = t >> 5;
    const int wm = wid >> 2, wn = wid & 3;        // 2x4 warps, 64x32 tiles
    const int m0 = blockIdx.y * 128, n0 = blockIdx.x * 128;
    const int zHi = blockIdx.z >> 4, zLo = blockIdx.z & 15;

    const u16* Ag = A + (long long)zHi * aHi + (long long)zLo * aLo;
    const u16* Bg = Bm + (long long)zHi * bHi + (long long)zLo * bLo;

    float acc[4][4][4];
#pragma unroll
    for (int i = 0; i < 4; i++)
#pragma unroll
        for (int j = 0; j < 4; j++)
#pragma unroll
            for (int e = 0; e < 4; e++) acc[i][j][e] = 0.f;

    const int nslab = Kp >> 5;
    const int lrow = t >> 2, lc16 = t & 3;

    auto load_stage = [&](int slab, int stg) {
        const uint32_t base = sb + (uint32_t)stg * 20480u;
        const int k0 = slab << 5;
        cpasync16(base + lrow * 80 + lc16 * 16,
                  Ag + (long long)(m0 + lrow) * Kp + k0 + lc16 * 8);
        cpasync16(base + 10240 + lrow * 80 + lc16 * 16,
                  Bg + (long long)(n0 + lrow) * Kp + k0 + lc16 * 8);
        cpasync16(base + (lrow + 64) * 80 + lc16 * 16,
                  Ag + (long long)(m0 + lrow + 64) * Kp + k0 + lc16 * 8);
        cpasync16(base + 10240 + (lrow + 64) * 80 + lc16 * 16,
                  Bg + (long long)(n0 + lrow + 64) * Kp + k0 + lc16 * 8);
    };

    const int r8 = lane & 7, jj = lane >> 3;
    auto compute = [&](int stg) {
        const uint32_t aB = sb + (uint32_t)stg * 20480u;
        const uint32_t bB = aB + 10240u;
#pragma unroll
        for (int k16 = 0; k16 < 2; k16++) {
            uint32_t af[4][4], bf[4][2];
#pragma unroll
            for (int mf = 0; mf < 4; mf++) {
                uint32_t ad = aB + (uint32_t)((wm * 64 + mf * 16 + r8 + (jj & 1) * 8) * 80
                                              + k16 * 32 + (jj >> 1) * 16);
                ldsm4(af[mf][0], af[mf][1], af[mf][2], af[mf][3], ad);
            }
#pragma unroll
            for (int p = 0; p < 2; p++) {
                uint32_t bd = bB + (uint32_t)((wn * 32 + p * 16 + r8 + (jj >> 1) * 8) * 80
                                              + k16 * 32 + (jj & 1) * 16);
                ldsm4(bf[2*p][0], bf[2*p][1], bf[2*p+1][0], bf[2*p+1][1], bd);
            }
#pragma unroll
            for (int mf = 0; mf < 4; mf++)
#pragma unroll
                for (int nf = 0; nf < 4; nf++)
                    mma_bf16(acc[mf][nf], af[mf], bf[nf]);
        }
    };

    // prologue: 3 stages
#pragma unroll
    for (int s = 0; s < 3; s++) {
        if (s < nslab) load_stage(s, s);
        CP_COMMIT();
    }
    for (int ks = 0; ks < nslab; ks++) {
        CP_WAIT2();
        __syncthreads();
        compute(ks & 3);
        int ns = ks + 3;
        if (ns < nslab) load_stage(ns, ns & 3);
        CP_COMMIT();
    }

    // ---- epilogue ----
    int tab[6];
    if (outSplit == 3) {
        if (side == 0) { tab[0]=0; tab[1]=0; tab[2]=1; tab[3]=0; tab[4]=1; tab[5]=2; }
        else           { tab[0]=0; tab[1]=1; tab[2]=0; tab[3]=2; tab[4]=1; tab[5]=0; }
    } else {
        if (side == 0) { tab[0]=0; tab[1]=0; tab[2]=1; }
        else           { tab[0]=0; tab[1]=1; tab[2]=0; }
    }
    const int nseg = (outSplit == 3) ? 6 : 3;

    float* outFz = outF ? outF + (long long)zHi * cHi + (long long)zLo * cLo : nullptr;
    u16* outPz = outP ? outP + (long long)zHi * pHi + (long long)zLo * pLo + pCo : nullptr;

    const int grp = lane >> 2, q = lane & 3;
    auto emit = [&](int grow, int gcol, float v0, float v1) {
        if (outSplit == 0) {
            if (bias) { v0 += bias[gcol]; v1 += bias[gcol + 1]; }
            float2 w; w.x = v0; w.y = v1;
            *(float2*)(outFz + (long long)grow * ldc + gcol) = w;
        } else {
            if (doRelu) { v0 = fmaxf(v0, 0.f); v1 = fmaxf(v1, 0.f); }
            int mm = gcol >> colShift, cc = gcol & colMask;
            if (vsc) {
                float s0 = (cc < ATT) ? vsc[mm * ATT + cc] : 0.f;
                float s1 = (cc + 1 < ATT) ? vsc[mm * ATT + cc + 1] : 0.f;
                v0 *= s0; v1 *= s1;
            }
            u16 pa[3], pb[3];
            if (outSplit == 3) { split3u(v0, pa[0], pa[1], pa[2]); split3u(v1, pb[0], pb[1], pb[2]); }
            else               { split2u(v0, pa[0], pa[1]); split2u(v1, pb[0], pb[1]); pa[2]=0; pb[2]=0; }
            u16* rb = outPz + (long long)mm * modStride + (long long)grow * ldp + cc;
#pragma unroll
            for (int s = 0; s < 6; s++) {
                if (s >= nseg) break;
                uint32_t w = (uint32_t)pa[tab[s]] | ((uint32_t)pb[tab[s]] << 16);
                *(uint32_t*)(rb + s * segW) = w;
            }
        }
    };

#pragma unroll
    for (int mf = 0; mf < 4; mf++)
#pragma unroll
        for (int nf = 0; nf < 4; nf++) {
            int gr = m0 + wm * 64 + mf * 16 + grp;
            int gc = n0 + wn * 32 + nf * 8 + q * 2;
            emit(gr,     gc, acc[mf][nf][0], acc[mf][nf][1]);
            emit(gr + 8, gc, acc[mf][nf][2], acc[mf][nf][3]);
        }
}

// ---------------------------------------------------------------------------
// Masked row softmax -> alpha planes (A-side split2)
// rows: [module][b][l] = 3*8192
// ---------------------------------------------------------------------------
__global__ void softmax_kernel(const float* __restrict__ S,
                               const unsigned char* __restrict__ mask,
                               u16* __restrict__ out) {
    int row = blockIdx.x;
    int b = (row >> 9) & 15;
    const float* s = S + (long long)row * LL;
    const unsigned char* m = mask + (long long)b * LL;
    int t = threadIdx.x;

    __shared__ float red[256];
    __shared__ float sv[LL];

    float mx = -3.402823466e38f;
    for (int i = t; i < LL; i += 256) {
        float v = m[i] ? -3.402823466e38f : s[i];
        sv[i] = v;
        mx = fmaxf(mx, v);
    }
    red[t] = mx; __syncthreads();
    for (int o = 128; o > 0; o >>= 1) {
        if (t < o) red[t] = fmaxf(red[t], red[t + o]);
        __syncthreads();
    }
    mx = red[0]; __syncthreads();

    float sum = 0.f;
    for (int i = t; i < LL; i += 256) {
        float e = __expf(sv[i] - mx);
        sv[i] = e;
        sum += e;
    }
    red[t] = sum; __syncthreads();
    for (int o = 128; o > 0; o >>= 1) {
        if (t < o) red[t] += red[t + o];
        __syncthreads();
    }
    float inv = 1.f / red[0];
    u16* o = out + (long long)row * KSE;
    for (int i = t; i < LL; i += 256) {
        float a = sv[i] * inv;
        u16 p0, p1; split2u(a, p0, p1);
        o[i] = p0; o[LL + i] = p0; o[2 * LL + i] = p1;
    }
}

// ---------------------------------------------------------------------------
// BiLSTM recurrence
// ---------------------------------------------------------------------------
__global__ __launch_bounds__(512, 1)
void lstm_kernel(const float* __restrict__ gin_f, const float* __restrict__ gin_b,
                 const float* __restrict__ Whh_f, const float* __restrict__ Whh_b,
                 float* __restrict__ out) {
    int blk = blockIdx.x;
    int dir = blk >> 4;
    int b = blk & 15;
    const float* gin = dir ? gin_b : gin_f;
    const float* W = dir ? Whh_b : Whh_f;
    int t = threadIdx.x;

    __shared__ float h_s[128];
    __shared__ float z_s[512];
    if (t < 128) h_s[t] = 0.f;
    float c = 0.f;
    const float4* w4 = reinterpret_cast<const float4*>(W + t * HH);
    __syncthreads();

    for (int step = 0; step < LL; step++) {
        int l = dir ? (LL - 1 - step) : step;
        float acc = gin[((long long)(b * LL + l)) * GATES + t];
#pragma unroll 8
        for (int k = 0; k < HH / 4; k++) {
            float4 w = __ldg(&w4[k]);
            float4 h = *reinterpret_cast<const float4*>(&h_s[k * 4]);
            acc += w.x * h.x + w.y * h.y + w.z * h.z + w.w * h.w;
        }
        z_s[t] = acc;
        __syncthreads();
        if (t < 128) {
            float zi = z_s[t], zf = z_s[128 + t], zg = z_s[256 + t], zo = z_s[384 + t];
            float ig = 1.f / (1.f + expf(-zi));
            float fg = 1.f / (1.f + expf(-zf));
            float gg = tanhf(zg);
            float og = 1.f / (1.f + expf(-zo));
            c = fg * c + ig * gg;
            float h = og * tanhf(c);
            h_s[t] = h;
            out[((long long)(b * LL + l)) * 256 + dir * HH + t] = h;
        }
        __syncthreads();
    }
}

// ---------------------------------------------------------------------------
// Launch orchestration
// ---------------------------------------------------------------------------
static void* symaddr(const void* sym) {
    void* p = nullptr;
    cudaGetSymbolAddress(&p, sym);
    return p;
}

extern "C" void kernel_launch(void* const* d_in, const int* in_sizes, int n_in,
                              void* d_out, int out_size) {
    const float* x1_word = (const float*)d_in[0];
    const float* x1_a0   = (const float*)d_in[1];
    const float* x1_a1   = (const float*)d_in[2];
    const float* x2_word = (const float*)d_in[3];
    const float* x2_a0   = (const float*)d_in[4];
    const float* x2_a1   = (const float*)d_in[5];
    const float* x2_a2   = (const float*)d_in[6];
    const unsigned char* x2_mask = (const unsigned char*)d_in[8];
    const float* W_attn  = (const float*)d_in[9];
    const float* v_attn  = (const float*)d_in[10];
    const float* Wih_f   = (const float*)d_in[11];
    const float* Whh_f   = (const float*)d_in[12];
    const float* b_f     = (const float*)d_in[13];
    const float* Wih_b   = (const float*)d_in[14];
    const float* Whh_b   = (const float*)d_in[15];
    const float* b_b     = (const float*)d_in[16];
    float* out = (float*)d_out;

    u16* x1e  = (u16*)symaddr(g_x1e);
    u16* x2e  = (u16*)symaddr(g_x2e);
    u16* We   = (u16*)symaddr(g_We);
    u16* r1e  = (u16*)symaddr(g_r1e);
    u16* r2e  = (u16*)symaddr(g_r2e);
    u16* ae   = (u16*)symaddr(g_ae);
    u16* x2Te = (u16*)symaddr(g_x2Te);
    u16* x1ce = (u16*)symaddr(g_x1ce);
    u16* Wihe = (u16*)symaddr(g_Wihe);
    float* scores = (float*)symaddr(g_scores);
    float* gin    = (float*)symaddr(g_gin);

    const int GSMEM = 4 * 20480;   // 80 KB
    cudaFuncSetAttribute(gemm_bf16, cudaFuncAttributeMaxDynamicSharedMemorySize, GSMEM);

    const float* x2_list[3] = {x2_a0, x2_a1, x2_a2};
    const int FULLMASK = (1 << 30) - 1;

    // 1) prep
    {
        long long n1 = (long long)ROWS * K1;
        prep_x3<<<(int)((n1 + 255) / 256), 256>>>(x1_word, x1_a0, x1_a1, x1e);
        prep_x3<<<(int)((n1 + 255) / 256), 256>>>(x2_word, x2_a0, x2_a1, x2e);
        long long nw = (long long)768 * K1;
        prep_W3<<<(int)((nw + 255) / 256), 256>>>(W_attn, We);
        long long nh = (long long)2 * GATES * RNN_IN;
        prep_Wih2<<<(int)((nh + 255) / 256), 256>>>(Wih_f, Wih_b, Wihe);
        long long nc = (long long)ROWS * 2 * AH;
        init_cat2<<<(int)((nc + 255) / 256), 256>>>(x1_a0, x1_a1, x1ce);
        dim3 tg(LL / 32, AH / 32, BB), tb(32, 8);
        for (int i = 0; i < 3; i++)
            transpose2<<<tg, tb>>>(x2_list[i], x2Te + (long long)i * BB * AH * KSE);
    }

    // 2) r1 = relu(x1_att @ W^T) -> split3 A-side planes (all 3 modules, N=768)
    gemm_bf16<<<dim3(6, 64, 1), 256, GSMEM>>>(
        x1e, We, 0, 0, 0, 0,
        nullptr, 0, 0, 0, nullptr, nullptr,
        r1e, 0, 0, 0, KRE, 256, (long long)ROWS * KRE, 8, 255,
        3, 0, 1, K1E);

    // 3) r2 = relu(x2_att @ W^T) * v -> split3 B-side planes (side=1!)
    gemm_bf16<<<dim3(6, 64, 1), 256, GSMEM>>>(
        x2e, We, 0, 0, 0, 0,
        nullptr, 0, 0, 0, nullptr, v_attn,
        r2e, 0, 0, 0, KRE, 256, (long long)ROWS * KRE, 8, 255,
        3, 1, 1, K1E);

    // 4) scores[m][b] = r1 @ r2^T  (fp32), z = m*16+b
    gemm_bf16<<<dim3(4, 4, 48), 256, GSMEM>>>(
        r1e, r2e,
        (long long)ROWS * KRE, (long long)LL * KRE,
        (long long)ROWS * KRE, (long long)LL * KRE,
        scores, (long long)BB * LL * LL, (long long)LL * LL, LL,
        nullptr, nullptr,
        nullptr, 0, 0, 0, 0, 0, 0, 30, FULLMASK,
        0, 0, 0, KRE);

    // 5) softmax -> alpha split2 planes
    softmax_kernel<<<3 * ROWS, 256>>>(scores, x2_mask, ae);

    // 6) piece[m][b] = alpha @ V -> x1cat cols [512+256m, +256), split2 A-side
    gemm_bf16<<<dim3(2, 4, 48), 256, GSMEM>>>(
        ae, x2Te,
        (long long)ROWS * KSE, (long long)LL * KSE,
        (long long)BB * AH * KSE, (long long)AH * KSE,
        nullptr, 0, 0, 0, nullptr, nullptr,
        x1ce, 256, (long long)LL * KCE, 512, KCE, RNN_IN, 0, 30, FULLMASK,
        2, 0, 0, KSE);

    // 7) gin[dir] = x1cat @ Wih^T + b  (fp32)
    gemm_bf16<<<dim3(4, 64, 1), 256, GSMEM>>>(
        x1ce, Wihe, 0, 0, 0, 0,
        gin, 0, 0, GATES, b_f, nullptr,
        nullptr, 0, 0, 0, 0, 0, 0, 30, FULLMASK,
        0, 0, 0, KCE);
    gemm_bf16<<<dim3(4, 64, 1), 256, GSMEM>>>(
        x1ce, Wihe + (long long)GATES * KCE, 0, 0, 0, 0,
        gin + (long long)ROWS * GATES, 0, 0, GATES, b_b, nullptr,
        nullptr, 0, 0, 0, 0, 0, 0, 30, FULLMASK,
        0, 0, 0, KCE);

    // 8) recurrence
    lstm_kernel<<<32, 512>>>(gin, gin + (long long)ROWS * GATES,
                             Whh_f, Whh_b, out);
}